// round 1
// baseline (speedup 1.0000x reference)
#include <cuda_runtime.h>
#include <math.h>

// Problem dims
#define Bn 64
#define Nn 256
#define Fn 16
#define Hn 256
#define ROWS (Bn*Nn)          // 16384
#define N_ITERS 10

// GEMM tile config
#define BM 128
#define BN 128
#define BK 8
#define TM 8
#define TN 8
#define PAD 4

// Scratch (static device allocations are the sanctioned workaround)
__device__ float g_h  [ROWS*Hn];
__device__ float g_t  [ROWS*Hn];
__device__ float g_m  [ROWS*Hn];
__device__ float g_z  [ROWS*Hn];
__device__ float g_rh [ROWS*Hn];
__device__ float g_jcz[ROWS*Hn];
__device__ float g_jcr[ROWS*Hn];
__device__ float g_jch[ROWS*Hn];
__device__ float g_t2 [ROWS*Hn];

enum { EPI_BIAS=0, EPI_TANH, EPI_SIG, EPI_SIG_MUL_H, EPI_GRU, EPI_TANH_BIAS };

__device__ __forceinline__ float sigf(float x){ return 1.0f/(1.0f+expf(-x)); }

// Generic fused GEMM:
//   C = epilogue( A @ B + extras )
// K can be 256 or 512. For K=512, k in [0,256) reads A0/B0, k in [256,512) reads A1/B1.
// batched=1: A0 and B0 are [64][256][256]; block's batch derived from row range.
// All matrices row-major, inner dim 256.
template<int EPI>
__global__ void __launch_bounds__(256) gemm_k(
    const float* __restrict__ A0, const float* __restrict__ A1,
    const float* __restrict__ B0, const float* __restrict__ B1,
    const float* __restrict__ bias,   // per-col [256] (may be null)
    const float* jc,                  // per-element [ROWS,256] (may be null)
    const float* Hb,                  // h buffer for epilogue (may be null)
    const float* Zb,                  // z buffer for epilogue (may be null)
    float* C, int K, int batched)
{
    __shared__ float As[BK][BM+PAD];
    __shared__ float Bs[BK][BN+PAD];

    const int tid = threadIdx.x;
    const int bn  = blockIdx.x * BN;
    const int bm  = blockIdx.y * BM;
    const int batch = batched ? (bm >> 8) : 0;
    const size_t boff = (size_t)batch * (Nn*Hn);
    const float* Ab = A0 + (batched ? boff : 0);
    const float* Bb = B0 + (batched ? boff : 0);
    const int am = batched ? (bm & (Nn-1)) : bm;   // row base within A matrix

    const int arow = tid >> 1, acol = (tid & 1) << 2;   // A tile: 128x8, 1 float4/thread
    const int brow = tid >> 5, bcol = (tid & 31) << 2;  // B tile: 8x128, 1 float4/thread
    const int tr = (tid >> 4) * TM, tc = (tid & 15) * TN;

    float acc[TM][TN];
    #pragma unroll
    for (int i = 0; i < TM; i++)
        #pragma unroll
        for (int j = 0; j < TN; j++) acc[i][j] = 0.0f;

    for (int kb = 0; kb < K; kb += BK) {
        const float* Aseg; const float* Bseg; int kk;
        if (kb < 256) { Aseg = Ab; Bseg = Bb; kk = kb; }
        else          { Aseg = A1; Bseg = B1; kk = kb - 256; }

        float4 av = *(const float4*)(Aseg + (size_t)(am + arow)*Hn + kk + acol);
        As[acol+0][arow] = av.x;
        As[acol+1][arow] = av.y;
        As[acol+2][arow] = av.z;
        As[acol+3][arow] = av.w;
        float4 bv = *(const float4*)(Bseg + (size_t)(kk + brow)*Hn + bn + bcol);
        *(float4*)(&Bs[brow][bcol]) = bv;
        __syncthreads();

        #pragma unroll
        for (int k = 0; k < BK; k++) {
            float4 a0 = *(const float4*)(&As[k][tr]);
            float4 a1 = *(const float4*)(&As[k][tr+4]);
            float4 b0 = *(const float4*)(&Bs[k][tc]);
            float4 b1 = *(const float4*)(&Bs[k][tc+4]);
            float ar[TM] = {a0.x,a0.y,a0.z,a0.w,a1.x,a1.y,a1.z,a1.w};
            float bc[TN] = {b0.x,b0.y,b0.z,b0.w,b1.x,b1.y,b1.z,b1.w};
            #pragma unroll
            for (int i = 0; i < TM; i++)
                #pragma unroll
                for (int j = 0; j < TN; j++)
                    acc[i][j] = fmaf(ar[i], bc[j], acc[i][j]);
        }
        __syncthreads();
    }

    #pragma unroll
    for (int i = 0; i < TM; i++) {
        const int row = bm + tr + i;
        #pragma unroll
        for (int j = 0; j < TN; j++) {
            const int col = bn + tc + j;
            const size_t idx = (size_t)row * Hn + col;
            float v = acc[i][j];
            if (EPI == EPI_BIAS) {
                v += bias[col];
            } else if (EPI == EPI_TANH) {
                v = tanhf(v);
            } else if (EPI == EPI_TANH_BIAS) {
                v = tanhf(v + bias[col]);
            } else if (EPI == EPI_SIG) {
                v = sigf(v + jc[idx]);
            } else if (EPI == EPI_SIG_MUL_H) {
                v = sigf(v + jc[idx]) * Hb[idx];        // rh = sigmoid(.) * h
            } else if (EPI == EPI_GRU) {
                float ht = tanhf(v + jc[idx]);
                float hv = Hb[idx];
                float zv = Zb[idx];
                v = hv + zv * (ht - hv);                // (1-z)*h + z*h~
            }
            C[idx] = v;
        }
    }
}

// Embedding: h = tanh(jets @ W_emb + b_emb). One block per row (K=16).
__global__ void emb_kernel(const float* __restrict__ jets,
                           const float* __restrict__ W_emb,
                           const float* __restrict__ b_emb,
                           float* __restrict__ h)
{
    const int row = blockIdx.x;
    const int j = threadIdx.x;
    __shared__ float sj[Fn];
    if (j < Fn) sj[j] = jets[(size_t)row*Fn + j];
    __syncthreads();
    float acc = b_emb[j];
    #pragma unroll
    for (int k = 0; k < Fn; k++)
        acc = fmaf(sj[k], W_emb[k*Hn + j], acc);
    h[(size_t)row*Hn + j] = tanhf(acc);
}

// Iteration-invariant jets contributions: jc_* = jets @ W*[H:H+F] + b*
__global__ void jc_kernel(const float* __restrict__ jets,
                          const float* __restrict__ Wz, const float* __restrict__ Wr,
                          const float* __restrict__ Wh,
                          const float* __restrict__ bz, const float* __restrict__ br,
                          const float* __restrict__ bh,
                          float* jcz, float* jcr, float* jch)
{
    const int row = blockIdx.x;
    const int j = threadIdx.x;
    __shared__ float sj[Fn];
    if (j < Fn) sj[j] = jets[(size_t)row*Fn + j];
    __syncthreads();
    float az = bz[j], ar = br[j], ah = bh[j];
    #pragma unroll
    for (int k = 0; k < Fn; k++) {
        const float s = sj[k];
        const int widx = (Hn + k) * Hn + j;
        az = fmaf(s, Wz[widx], az);
        ar = fmaf(s, Wr[widx], ar);
        ah = fmaf(s, Wh[widx], ah);
    }
    const size_t idx = (size_t)row*Hn + j;
    jcz[idx] = az; jcr[idx] = ar; jch[idx] = ah;
}

// Deterministic per-batch node-sum reduction: out[b,j] = sum_n t2[b,n,j]
__global__ void reduce_kernel(const float* __restrict__ t2, float* __restrict__ out)
{
    const int idx = blockIdx.x * blockDim.x + threadIdx.x;  // 0..16383
    const int b = idx >> 8;
    const int j = idx & 255;
    const float* p = t2 + (size_t)b * (Nn*Hn) + j;
    float acc = 0.0f;
    for (int n = 0; n < Nn; n++) acc += p[(size_t)n * Hn];
    out[idx] = acc;
}

extern "C" void kernel_launch(void* const* d_in, const int* in_sizes, int n_in,
                              void* d_out, int out_size)
{
    const float* jets  = (const float*)d_in[0];
    const float* dads  = (const float*)d_in[1];
    const float* W_emb = (const float*)d_in[2];
    const float* b_emb = (const float*)d_in[3];
    const float* W_msg = (const float*)d_in[4];
    const float* b_msg = (const float*)d_in[5];
    const float* Wz    = (const float*)d_in[6];
    const float* Uz    = (const float*)d_in[7];
    const float* bz    = (const float*)d_in[8];
    const float* Wr    = (const float*)d_in[9];
    const float* Ur    = (const float*)d_in[10];
    const float* br    = (const float*)d_in[11];
    const float* Wh    = (const float*)d_in[12];
    const float* Uh    = (const float*)d_in[13];
    const float* bh    = (const float*)d_in[14];
    const float* W_r1  = (const float*)d_in[15];
    const float* b_r1  = (const float*)d_in[16];
    const float* W_r2  = (const float*)d_in[17];
    const float* b_r2  = (const float*)d_in[18];
    float* out = (float*)d_out;

    float *h,*t,*m,*z,*rh,*jcz,*jcr,*jch,*t2;
    cudaGetSymbolAddress((void**)&h,   g_h);
    cudaGetSymbolAddress((void**)&t,   g_t);
    cudaGetSymbolAddress((void**)&m,   g_m);
    cudaGetSymbolAddress((void**)&z,   g_z);
    cudaGetSymbolAddress((void**)&rh,  g_rh);
    cudaGetSymbolAddress((void**)&jcz, g_jcz);
    cudaGetSymbolAddress((void**)&jcr, g_jcr);
    cudaGetSymbolAddress((void**)&jch, g_jch);
    cudaGetSymbolAddress((void**)&t2,  g_t2);

    dim3 grid(Hn/BN, ROWS/BM);   // (2, 128) = 256 blocks

    // h0 = tanh(jets @ W_emb + b_emb)
    emb_kernel<<<ROWS, Hn>>>(jets, W_emb, b_emb, h);
    // jc_* = jets @ W*[H:] + b*   (iteration-invariant)
    jc_kernel<<<ROWS, Hn>>>(jets, Wz, Wr, Wh, bz, br, bh, jcz, jcr, jch);

    for (int it = 0; it < N_ITERS; it++) {
        // t = h @ W_msg + b_msg
        gemm_k<EPI_BIAS><<<grid, 256>>>(h, nullptr, W_msg, nullptr, b_msg,
                                        nullptr, nullptr, nullptr, t, 256, 0);
        // m = tanh(dads @ t)   (batched per b)
        gemm_k<EPI_TANH><<<grid, 256>>>(dads, nullptr, t, nullptr, nullptr,
                                        nullptr, nullptr, nullptr, m, 256, 1);
        // z = sigmoid(m@Wz[:H] + h@Uz + jc_z)
        gemm_k<EPI_SIG><<<grid, 256>>>(m, h, Wz, Uz, nullptr,
                                       jcz, nullptr, nullptr, z, 512, 0);
        // rh = sigmoid(m@Wr[:H] + h@Ur + jc_r) * h
        gemm_k<EPI_SIG_MUL_H><<<grid, 256>>>(m, h, Wr, Ur, nullptr,
                                             jcr, h, nullptr, rh, 512, 0);
        // h = (1-z)*h + z*tanh(m@Wh[:H] + rh@Uh + jc_h)
        gemm_k<EPI_GRU><<<grid, 256>>>(m, rh, Wh, Uh, nullptr,
                                       jch, h, z, h, 512, 0);
    }

    // readout: t = tanh(h@W_r1 + b_r1); t2 = t@W_r2 + b_r2; out = sum_n t2
    gemm_k<EPI_TANH_BIAS><<<grid, 256>>>(h, nullptr, W_r1, nullptr, b_r1,
                                         nullptr, nullptr, nullptr, t, 256, 0);
    gemm_k<EPI_BIAS><<<grid, 256>>>(t, nullptr, W_r2, nullptr, b_r2,
                                    nullptr, nullptr, nullptr, t2, 256, 0);
    reduce_kernel<<<Bn, 256>>>(t2, out);
}